// round 1
// baseline (speedup 1.0000x reference)
#include <cuda_runtime.h>
#include <math.h>

#define NN 8192

// Scratch (no allocations allowed -> __device__ globals)
__device__ float g_A[NN];   // segment sums A[d] = p[d] + sum p[src] over in-edges
__device__ float g_S[NN];   // S per original node index
__device__ float g_V[NN];   // sorted copy of S
__device__ float g_C;       // dot(x, p)

// ---------------------------------------------------------------------------
// A[i] = p[i]  (self-loop contribution)
__global__ void k_init(const float* __restrict__ p, int n) {
    int i = blockIdx.x * blockDim.x + threadIdx.x;
    if (i < n) g_A[i] = p[i];
}

// ---------------------------------------------------------------------------
// C = dot(x[:,0], p)  -- deterministic double-precision tree reduction, 1 block
__global__ void k_dot(const float* __restrict__ x, const float* __restrict__ p, int n) {
    __shared__ double sh[1024];
    int t = threadIdx.x;
    double acc = 0.0;
    for (int i = t; i < n; i += 1024)
        acc += (double)x[i] * (double)p[i];
    sh[t] = acc;
    __syncthreads();
    for (int s = 512; s > 0; s >>= 1) {
        if (t < s) sh[t] += sh[t + s];
        __syncthreads();
    }
    if (t == 0) g_C = (float)sh[0];
}

// ---------------------------------------------------------------------------
// Scatter-add over edges: A[dst] += p[src].
// p values are integer-valued floats; total per node < 2^24 -> exact & deterministic.
__global__ void k_edges(const int* __restrict__ ei, const float* __restrict__ p, int E) {
    int e = blockIdx.x * blockDim.x + threadIdx.x;
    if (e < E) {
        int s = ei[e];       // row 0: src
        int d = ei[E + e];   // row 1: dst
        atomicAdd(&g_A[d], p[s]);
    }
}

// ---------------------------------------------------------------------------
// S[i] = p[i]*log(n) + log(A[i]) + C   (closed form of the segment logsumexp)
__global__ void k_S(const float* __restrict__ p, int n, float logn) {
    int i = blockIdx.x * blockDim.x + threadIdx.x;
    if (i < n) {
        float lse = p[i] * logn + logf(g_A[i]);
        float s = lse + g_C;
        g_S[i] = s;
        g_V[i] = s;
    }
}

// ---------------------------------------------------------------------------
// Single-block bitonic sort of n (power of two) floats in shared memory.
__global__ void k_sort(int n) {
    extern __shared__ float v[];
    int t = threadIdx.x;
    int T = blockDim.x;
    for (int i = t; i < n; i += T) v[i] = g_V[i];

    for (int k = 2; k <= n; k <<= 1) {
        for (int j = k >> 1; j > 0; j >>= 1) {
            __syncthreads();
            for (int i = t; i < n; i += T) {
                int ixj = i ^ j;
                if (ixj > i) {
                    float a = v[i];
                    float b = v[ixj];
                    bool up = ((i & k) == 0);
                    if ((a > b) == up) {
                        v[i] = b;
                        v[ixj] = a;
                    }
                }
            }
        }
    }
    __syncthreads();
    for (int i = t; i < n; i += T) g_V[i] = v[i];
}

// ---------------------------------------------------------------------------
// out[i] = sum_j tanh(K*(S_i - S_j) - EPS)
//        = (#saturated +1) - (#saturated -1) + sum over narrow band of tanhf.
// arg(k) = K*(S_i - V[k]) - EPS is monotone non-increasing in k (V sorted
// ascending), so the band boundaries come from two binary searches.
__global__ void k_out(float* __restrict__ out, int n) {
    extern __shared__ float v[];
    int t = threadIdx.x;
    int T = blockDim.x;
    for (int i = t; i < n; i += T) v[i] = g_V[i];
    __syncthreads();

    int i = blockIdx.x * T + t;
    if (i >= n) return;

    const float K   = 1000.0f;
    const float EPS = 5.0f;
    const float CUT = 10.0f;   // tanhf saturates to exactly +/-1.0f beyond ~9

    float Si = g_S[i];

    // loIdx: first k with arg <= CUT (everything before contributes exactly +1)
    int lo = 0, hi = n;
    while (lo < hi) {
        int m = (lo + hi) >> 1;
        float arg = K * (Si - v[m]) - EPS;
        if (arg > CUT) lo = m + 1; else hi = m;
    }
    int loIdx = lo;

    // hiIdx: first k with arg < -CUT (everything from there contributes -1)
    hi = n;  // lo == loIdx, valid lower bound (monotone predicate)
    while (lo < hi) {
        int m = (lo + hi) >> 1;
        float arg = K * (Si - v[m]) - EPS;
        if (arg >= -CUT) lo = m + 1; else hi = m;
    }
    int hiIdx = lo;

    float s = (float)loIdx - (float)(n - hiIdx);
    for (int m2 = loIdx; m2 < hiIdx; m2++)
        s += tanhf(K * (Si - v[m2]) - EPS);

    out[i] = s;
}

// ---------------------------------------------------------------------------
extern "C" void kernel_launch(void* const* d_in, const int* in_sizes, int n_in,
                              void* d_out, int out_size) {
    const int*   ei = (const int*)d_in[0];     // edge_index, (2, E) row-major
    const float* p  = (const float*)d_in[1];   // (N,)
    const float* x  = (const float*)d_in[2];   // (N, 1)

    int E = in_sizes[0] / 2;
    int n = in_sizes[1];
    float logn = logf((float)n);

    k_init<<<(n + 255) / 256, 256>>>(p, n);
    k_dot<<<1, 1024>>>(x, p, n);
    k_edges<<<(E + 255) / 256, 256>>>(ei, p, E);
    k_S<<<(n + 255) / 256, 256>>>(p, n, logn);
    k_sort<<<1, 1024, n * (int)sizeof(float)>>>(n);
    k_out<<<(n + 1023) / 1024, 1024, n * (int)sizeof(float)>>>((float*)d_out, n);
}

// round 2
// speedup vs baseline: 2.5706x; 2.5706x over previous
#include <cuda_runtime.h>
#include <math.h>

#define NN     8192
#define NB     8192
#define RANGEF 74000.0f
#define INV_W  ((float)NB / RANGEF)

// Scratch (__device__ globals; zero-initialized at load, self-restoring so
// every invocation sees the same initial state).
__device__ float g_A[NN];      // edge segment sums (starts 0, reset by k2)
__device__ float g_S[NN];      // S per node
__device__ float g_V[NN];      // bucket-grouped copy of S
__device__ int   g_H[NB];      // histogram (starts 0, reset by k3)
__device__ int   g_P[NB + 1];  // exclusive prefix of histogram
__device__ float g_C;          // dot(x, p)

// Monotone bucket map. MUST be identical at insert (k2/k3) and query (k4).
__device__ __forceinline__ int bucket_of(float v, float C) {
    float u = (v - C) * INV_W;
    int b = (int)u;
    if (b < 0) b = 0;
    if (b > NB - 1) b = NB - 1;
    return b;
}

// ---------------------------------------------------------------------------
// Block 0: C = dot(x, p) via deterministic double-precision tree.
// Blocks 1..: A[dst] += p[src] (exact: p integer-valued, sums < 2^24).
__global__ void k1_edges_dot(const int* __restrict__ ei,
                             const float* __restrict__ p,
                             const float* __restrict__ x,
                             int E, int n) {
    if (blockIdx.x == 0) {
        __shared__ double sh[1024];
        int t = threadIdx.x;
        double acc = 0.0;
        for (int i = t; i < n; i += 1024)
            acc += (double)x[i] * (double)p[i];
        sh[t] = acc;
        __syncthreads();
        for (int s = 512; s > 0; s >>= 1) {
            if (t < s) sh[t] += sh[t + s];
            __syncthreads();
        }
        if (t == 0) g_C = (float)sh[0];
    } else {
        int e = (blockIdx.x - 1) * 1024 + threadIdx.x;
        if (e < E) {
            int s = ei[e];       // row 0: src
            int d = ei[E + e];   // row 1: dst
            atomicAdd(&g_A[d], p[s]);
        }
    }
}

// ---------------------------------------------------------------------------
// S[i] = p[i]*log(n) + log(p[i] + A[i]) + C ; reset A; build histogram.
__global__ void k2_S_hist(const float* __restrict__ p, int n, float logn) {
    int i = blockIdx.x * blockDim.x + threadIdx.x;
    if (i < n) {
        float A  = g_A[i];
        g_A[i]   = 0.0f;                       // restore invariant for next run
        float pi = p[i];
        float C  = g_C;
        float s  = pi * logn + logf(pi + A) + C;
        g_S[i]   = s;
        atomicAdd(&g_H[bucket_of(s, C)], 1);
    }
}

// ---------------------------------------------------------------------------
// Single block: exclusive scan of 8192 bins, write g_P, zero g_H,
// then counting-sort scatter of S into g_V (grouped by bucket).
__global__ void k3_scan_scatter(int n) {
    __shared__ int Ps[NB];       // per-bin exclusive prefix, then live counters
    __shared__ int bs[1024];     // block scan workspace
    int t = threadIdx.x;

    // Load this thread's 8 bins; zero them in global for the next run.
    int c[8];
    int base = t * 8;
#pragma unroll
    for (int k = 0; k < 8; k++) {
        c[k] = g_H[base + k];
        g_H[base + k] = 0;
    }
    // Local serial exclusive prefix + thread total.
    int tot = 0;
    int ex[8];
#pragma unroll
    for (int k = 0; k < 8; k++) { ex[k] = tot; tot += c[k]; }

    // Inclusive Hillis-Steele scan over 1024 thread totals.
    bs[t] = tot;
    __syncthreads();
    for (int off = 1; off < 1024; off <<= 1) {
        int v = (t >= off) ? bs[t - off] : 0;
        __syncthreads();
        bs[t] += v;
        __syncthreads();
    }
    int excl = bs[t] - tot;

#pragma unroll
    for (int k = 0; k < 8; k++) {
        int pref = excl + ex[k];
        Ps[base + k]     = pref;
        g_P[base + k]    = pref;
    }
    if (t == 1023) g_P[NB] = bs[1023];   // total = n
    __syncthreads();                     // g_P snapshot done; Ps now counters

    // Scatter: 8 elements per thread.
    float C = g_C;
#pragma unroll
    for (int k = 0; k < 8; k++) {
        int i = t * 8 + k;
        if (i < n) {
            float s = g_S[i];
            int b = bucket_of(s, C);
            int pos = atomicAdd(&Ps[b], 1);
            g_V[pos] = s;
        }
    }
}

// ---------------------------------------------------------------------------
// out[i] = sum_j tanh(1000*(S_i - S_j) - 5)
// Outside band [Si-0.015, Si+0.005]: exactly saturated (+1 / -1) -> prefix
// counts. Band buckets: exact per-element evaluation (incl. diagonal j=i).
__global__ void k4_out(float* __restrict__ out, int n) {
    int i = blockIdx.x * blockDim.x + threadIdx.x;
    if (i >= n) return;

    const float K   = 1000.0f;
    const float EPS = 5.0f;
    const float CUT = 10.0f;

    float C  = g_C;
    float Si = g_S[i];

    int loB = bucket_of(Si - 0.015f, C);   // all buckets < loB: arg > ~14.9 -> +1
    int hiB = bucket_of(Si + 0.005f, C);   // all buckets > hiB: arg < ~-10  -> -1

    float acc = (float)g_P[loB] - (float)(n - g_P[hiB + 1]);

    for (int b = loB; b <= hiB; ++b) {
        int s0 = g_P[b];
        int e0 = g_P[b + 1];
        for (int idx = s0; idx < e0; ++idx) {
            float w   = g_V[idx];
            float arg = K * (Si - w) - EPS;
            if (arg > CUT)        acc += 1.0f;
            else if (arg < -CUT)  acc -= 1.0f;
            else                  acc += tanhf(arg);
        }
    }
    out[i] = acc;
}

// ---------------------------------------------------------------------------
extern "C" void kernel_launch(void* const* d_in, const int* in_sizes, int n_in,
                              void* d_out, int out_size) {
    const int*   ei = (const int*)d_in[0];     // (2, E) row-major
    const float* p  = (const float*)d_in[1];   // (N,)
    const float* x  = (const float*)d_in[2];   // (N, 1)

    int E = in_sizes[0] / 2;
    int n = in_sizes[1];
    float logn = logf((float)n);

    int edgeBlocks = (E + 1023) / 1024;
    k1_edges_dot<<<1 + edgeBlocks, 1024>>>(ei, p, x, E, n);
    k2_S_hist<<<(n + 1023) / 1024, 1024>>>(p, n, logn);
    k3_scan_scatter<<<1, 1024>>>(n);
    k4_out<<<(n + 1023) / 1024, 1024>>>((float*)d_out, n);
}

// round 3
// speedup vs baseline: 2.7759x; 1.0799x over previous
#include <cuda_runtime.h>
#include <math.h>

#define NN     8192
#define NB     8192
#define RANGEF 74000.0f
#define INV_W  ((float)NB / RANGEF)

// Scratch (__device__ globals; zero-initialized at load; g_A is self-restoring
// so every invocation sees the same initial state).
__device__ float g_A[NN];      // edge segment sums (starts 0, reset by k2)
__device__ float g_S[NN];      // S per node (original order)
__device__ float g_V[NN];      // bucket-grouped copy of S
__device__ int   g_P[NB + 1];  // exclusive prefix of bucket histogram
__device__ float g_C;          // dot(x, p)

// Monotone bucket map. MUST be identical at insert (k2) and query (k3).
__device__ __forceinline__ int bucket_of(float v, float C) {
    float u = (v - C) * INV_W;
    int b = (int)u;
    if (b < 0) b = 0;
    if (b > NB - 1) b = NB - 1;
    return b;
}

// ---------------------------------------------------------------------------
// Block 0: C = dot(x, p) via deterministic double-precision tree.
// Blocks 1..: A[dst] += p[src], 2 edges per thread (exact: p integer-valued,
// per-node sums < 2^24 -> atomicAdd is order-independent).
__global__ void k1_edges_dot(const int* __restrict__ ei,
                             const float* __restrict__ p,
                             const float* __restrict__ x,
                             int E, int n) {
    if (blockIdx.x == 0) {
        __shared__ double sh[1024];
        int t = threadIdx.x;
        double acc = 0.0;
        for (int i = t; i < n; i += 1024)
            acc += (double)x[i] * (double)p[i];
        sh[t] = acc;
        __syncthreads();
        for (int s = 512; s > 0; s >>= 1) {
            if (t < s) sh[t] += sh[t + s];
            __syncthreads();
        }
        if (t == 0) g_C = (float)sh[0];
    } else {
        int base = (blockIdx.x - 1) * 2048 + threadIdx.x;
        int e0 = base;
        int e1 = base + 1024;
        if (e0 < E) {
            int s = __ldg(&ei[e0]);
            int d = __ldg(&ei[E + e0]);
            atomicAdd(&g_A[d], __ldg(&p[s]));
        }
        if (e1 < E) {
            int s = __ldg(&ei[e1]);
            int d = __ldg(&ei[E + e1]);
            atomicAdd(&g_A[d], __ldg(&p[s]));
        }
    }
}

// ---------------------------------------------------------------------------
// Single block, 1024 threads: S = p*logn + log(p + A) + C, smem histogram,
// warp-shuffle exclusive scan over 8192 bins, publish prefix g_P, counting-
// sort scatter of S into g_V. g_A reset for the next invocation.
__global__ void k2_build(const float* __restrict__ p, int n, float logn) {
    __shared__ int cnt[NB];     // histogram -> prefix -> live counters
    __shared__ int wsum[32];
    int t = threadIdx.x;

#pragma unroll
    for (int k = 0; k < 8; k++) cnt[t + 1024 * k] = 0;
    float C = g_C;
    __syncthreads();

    // Compute S (strided, coalesced), histogram into smem.
    float sv[8];
    int   bk[8];
#pragma unroll
    for (int k = 0; k < 8; k++) {
        int i = t + 1024 * k;
        float A  = g_A[i];
        g_A[i]   = 0.0f;                     // restore invariant
        float pi = p[i];
        float s  = pi * logn + logf(pi + A) + C;
        sv[k] = s;
        g_S[i] = s;
        int b = bucket_of(s, C);
        bk[k] = b;
        atomicAdd(&cnt[b], 1);
    }
    __syncthreads();

    // Exclusive scan of 8192 bins: 8 serial per thread + warp-shuffle scan.
    int base = t * 8;
    int ex[8];
    int tot = 0;
#pragma unroll
    for (int k = 0; k < 8; k++) { ex[k] = tot; tot += cnt[base + k]; }

    int lane = t & 31, wid = t >> 5;
    int v = tot;
#pragma unroll
    for (int o = 1; o < 32; o <<= 1) {
        int u = __shfl_up_sync(0xffffffffu, v, o);
        if (lane >= o) v += u;
    }
    if (lane == 31) wsum[wid] = v;
    __syncthreads();
    if (wid == 0) {
        int w = wsum[lane];
#pragma unroll
        for (int o = 1; o < 32; o <<= 1) {
            int u = __shfl_up_sync(0xffffffffu, w, o);
            if (lane >= o) w += u;
        }
        wsum[lane] = w;
    }
    __syncthreads();
    int excl = v - tot + (wid ? wsum[wid - 1] : 0);

#pragma unroll
    for (int k = 0; k < 8; k++) {
        int pref = excl + ex[k];
        cnt[base + k] = pref;    // live counter for scatter
        g_P[base + k] = pref;    // published prefix for k3
    }
    if (t == 1023) g_P[NB] = excl + tot;   // = n
    __syncthreads();

    // Counting-sort scatter.
#pragma unroll
    for (int k = 0; k < 8; k++) {
        int pos = atomicAdd(&cnt[bk[k]], 1);
        g_V[pos] = sv[k];
    }
}

// ---------------------------------------------------------------------------
// out[i] = sum_j tanh(1000*(S_i - S_j) - 5).
// Outside band [Si-0.015, Si+0.005]: exactly saturated (+1 / -1) -> prefix
// counts. Band buckets: exact per-element evaluation (incl. diagonal j=i).
__global__ void k3_out(float* __restrict__ out, int n) {
    int i = blockIdx.x * blockDim.x + threadIdx.x;
    if (i >= n) return;

    const float K   = 1000.0f;
    const float EPS = 5.0f;
    const float CUT = 10.0f;

    float C  = g_C;
    float Si = g_S[i];

    int loB = bucket_of(Si - 0.015f, C);   // buckets < loB: arg > ~10 -> +1
    int hiB = bucket_of(Si + 0.005f, C);   // buckets > hiB: arg < ~-10 -> -1

    int pLo = g_P[loB];
    int pHi = g_P[hiB + 1];
    float acc = (float)pLo - (float)(n - pHi);

    for (int idx = pLo; idx < pHi; ++idx) {
        float w   = g_V[idx];
        float arg = K * (Si - w) - EPS;
        if (arg > CUT)        acc += 1.0f;
        else if (arg < -CUT)  acc -= 1.0f;
        else                  acc += tanhf(arg);
    }
    out[i] = acc;
}

// ---------------------------------------------------------------------------
extern "C" void kernel_launch(void* const* d_in, const int* in_sizes, int n_in,
                              void* d_out, int out_size) {
    const int*   ei = (const int*)d_in[0];     // (2, E) row-major
    const float* p  = (const float*)d_in[1];   // (N,)
    const float* x  = (const float*)d_in[2];   // (N, 1)

    int E = in_sizes[0] / 2;
    int n = in_sizes[1];
    float logn = logf((float)n);

    int edgeBlocks = (E + 2047) / 2048;
    k1_edges_dot<<<1 + edgeBlocks, 1024>>>(ei, p, x, E, n);
    k2_build<<<1, 1024>>>(p, n, logn);
    k3_out<<<(n + 127) / 128, 128>>>((float*)d_out, n);
}